// round 14
// baseline (speedup 1.0000x reference)
#include <cuda_runtime.h>
#include <cuda_fp16.h>
#include <string.h>

// BAHDANAUplus — R11 (= R10 with fixed half2<->uint bit-cast):
// all per-dim arithmetic in packed half2 (HFMA2/HADD2).
// 16 lanes/sample, 2 samples/warp, 2 dims/lane packed in one half2.
// Embeddings converted to half2 once at load; weights half2 in registers;
// both warp reductions run on packed half2; scalar math (attn logits a0-a2,
// relu/W2/sigmoid epilogue) stays f32. Depth-3 software pipeline retained.

#define FULLMASK 0xffffffffu

__device__ __forceinline__ __half2 shfl_xor_h2(__half2 v, int off) {
    unsigned u;
    memcpy(&u, &v, 4);
    u = __shfl_xor_sync(FULLMASK, u, off);
    __half2 r;
    memcpy(&r, &u, 4);
    return r;
}

__global__ __launch_bounds__(128, 5) void bahdanau_kernel(
    const int*   __restrict__ group_inputs,
    const int*   __restrict__ item_inputs,
    const int*   __restrict__ members,
    const float* __restrict__ user_emb,
    const float* __restrict__ item_emb,
    const float* __restrict__ genres,
    const float* __restrict__ attn_W,
    const float* __restrict__ attn_b,
    const float* __restrict__ pred_W1,
    const float* __restrict__ pred_b1,
    const float* __restrict__ pred_W2,
    const float* __restrict__ pred_b2,
    float*       __restrict__ out,
    int n)
{
    const int lane = threadIdx.x & 31;
    const int sub  = lane & 15;          // position within the sample's 16-lane group
    const int half = lane >> 4;          // which sample of the pair
    const int wid  = threadIdx.x >> 5;
    const int gw   = blockIdx.x * 4 + wid;
    const int nwarp  = gridDim.x * 4;
    const int stride = nwarp * 2;        // samples consumed per iteration

    const int d0 = sub * 2;              // this lane's first dim

    // ---- attn_W packed: awh[seg][k] = (W[seg*32+d0][k], W[seg*32+d0+1][k]) ----
    __half2 awh[4][3];
    #pragma unroll
    for (int seg = 0; seg < 4; seg++) {
        const float2* p = (const float2*)(attn_W + (seg * 32 + d0) * 3);
        const float2 q0 = p[0], q1 = p[1], q2 = p[2];
        awh[seg][0] = __floats2half2_rn(q0.x, q1.y);
        awh[seg][1] = __floats2half2_rn(q0.y, q2.x);
        awh[seg][2] = __floats2half2_rn(q1.x, q2.y);
    }

    // ---- pred_W1 packed: w1h[seg][j] = (W1[seg*32+d0][j], W1[seg*32+d0+1][j]) ----
    __half2 w1h[3][8];
    #pragma unroll
    for (int seg = 0; seg < 3; seg++) {
        const float4* p0 = (const float4*)(pred_W1 + (seg * 32 + d0) * 8);
        const float4* p1 = (const float4*)(pred_W1 + (seg * 32 + d0 + 1) * 8);
        const float4 x0 = p0[0], x1 = p0[1];
        const float4 y0 = p1[0], y1 = p1[1];
        w1h[seg][0] = __floats2half2_rn(x0.x, y0.x);
        w1h[seg][1] = __floats2half2_rn(x0.y, y0.y);
        w1h[seg][2] = __floats2half2_rn(x0.z, y0.z);
        w1h[seg][3] = __floats2half2_rn(x0.w, y0.w);
        w1h[seg][4] = __floats2half2_rn(x1.x, y1.x);
        w1h[seg][5] = __floats2half2_rn(x1.y, y1.y);
        w1h[seg][6] = __floats2half2_rn(x1.z, y1.z);
        w1h[seg][7] = __floats2half2_rn(x1.w, y1.w);
    }

    const float ab0 = attn_b[0], ab1 = attn_b[1], ab2 = attn_b[2];
    const int   jm  = (lane >> 1) & 7;   // hidden unit owned after value-split
    const float b1j = pred_b1[jm];
    const float w2j = pred_W2[jm];
    const float b2  = pred_b2[0];

    const bool q3  = (lane & 8) != 0;
    const bool q2b = (lane & 4) != 0;
    const bool q1b = (lane & 2) != 0;

    const float2* ue = (const float2*)user_emb;   // 16 float2 per row
    const float2* ie = (const float2*)item_emb;   // 7 float2 per row
    const float2* ge = (const float2*)genres;     // 9 float2 per row

    int bc = gw * 2;                     // iteration base; my sample = bc + half
    if (bc >= n) return;

    // ---- prologue: fill 3-deep pipeline ----
    int  scur = bc + half;
    bool vC   = (scur < n);
    __half2 ec0, ec1, ec2, eci;          // current sample, half2-packed dims
    {
        const int sl = vC ? scur : 0;
        const int g  = group_inputs[sl];
        const int it = item_inputs[sl];
        const int m0 = members[3 * g + 0];
        const int m1 = members[3 * g + 1];
        const int m2 = members[3 * g + 2];
        const float2 a = ue[m0 * 16 + sub];
        const float2 b = ue[m1 * 16 + sub];
        const float2 c = ue[m2 * 16 + sub];
        const float2 d = (sub < 7) ? ie[it * 7 + sub] : ge[it * 9 + (sub - 7)];
        ec0 = __floats2half2_rn(a.x, a.y);
        ec1 = __floats2half2_rn(b.x, b.y);
        ec2 = __floats2half2_rn(c.x, c.y);
        eci = __floats2half2_rn(d.x, d.y);
    }

    int  bn  = bc + stride;
    __half2 en0, en1, en2v, eni;         // next sample
    {
        const int sx = bn + half;
        const int sl = (sx < n) ? sx : 0;
        const int g  = group_inputs[sl];
        const int it = item_inputs[sl];
        const int m0 = members[3 * g + 0];
        const int m1 = members[3 * g + 1];
        const int m2 = members[3 * g + 2];
        const float2 a = ue[m0 * 16 + sub];
        const float2 b = ue[m1 * 16 + sub];
        const float2 c = ue[m2 * 16 + sub];
        const float2 d = (sub < 7) ? ie[it * 7 + sub] : ge[it * 9 + (sub - 7)];
        en0  = __floats2half2_rn(a.x, a.y);
        en1  = __floats2half2_rn(b.x, b.y);
        en2v = __floats2half2_rn(c.x, c.y);
        eni  = __floats2half2_rn(d.x, d.y);
    }

    int bq = bn + stride;                // sample i+2: indices only
    int m2a, m2b, m2c, it2;
    {
        const int sx = bq + half;
        const int sl = (sx < n) ? sx : 0;
        const int g  = group_inputs[sl];
        it2 = item_inputs[sl];
        m2a = members[3 * g + 0];
        m2b = members[3 * g + 1];
        m2c = members[3 * g + 2];
    }

    for (;;) {
        // ---- stage 1: issue gathers for sample i+2 (consumed in 2 iters) ----
        const float2 fa = ue[m2a * 16 + sub];
        const float2 fb = ue[m2b * 16 + sub];
        const float2 fc = ue[m2c * 16 + sub];
        const float2 fd = (sub < 7) ? ie[it2 * 7 + sub] : ge[it2 * 9 + (sub - 7)];

        // ---- stage 2: prefetch index chain for sample i+3 ----
        const int br = bq + stride;
        int m3a, m3b, m3c, it3;
        {
            const int sx = br + half;
            const int sl = (sx < n) ? sx : 0;
            const int g  = group_inputs[sl];
            it3 = item_inputs[sl];
            m3a = members[3 * g + 0];
            m3b = members[3 * g + 1];
            m3c = members[3 * g + 2];
        }

        // ---- stage 3: compute current sample, all per-dim math in half2 ----
        // Attention partials: 4 HFMA2-class ops per logit.
        __half2 v0h = __hfma2(ec0, awh[0][0],
                      __hfma2(ec1, awh[1][0],
                      __hfma2(ec2, awh[2][0], __hmul2(eci, awh[3][0]))));
        __half2 v1h = __hfma2(ec0, awh[0][1],
                      __hfma2(ec1, awh[1][1],
                      __hfma2(ec2, awh[2][1], __hmul2(eci, awh[3][1]))));
        __half2 v2h = __hfma2(ec0, awh[0][2],
                      __hfma2(ec1, awh[1][2],
                      __hfma2(ec2, awh[2][2], __hmul2(eci, awh[3][2]))));

        // Butterfly over the 16-lane group, packed (one shfl covers 2 dims).
        #pragma unroll
        for (int off = 8; off > 0; off >>= 1) {
            v0h = __hadd2(v0h, shfl_xor_h2(v0h, off));
            v1h = __hadd2(v1h, shfl_xor_h2(v1h, off));
            v2h = __hadd2(v2h, shfl_xor_h2(v2h, off));
        }
        // Scalar logits in f32 (biases kept f32).
        const float a0 = __low2float(v0h) + __high2float(v0h) + ab0;
        const float a1 = __low2float(v1h) + __high2float(v1h) + ab1;
        const float a2 = __low2float(v2h) + __high2float(v2h) + ab2;
        const __half2 a0h = __float2half2_rn(a0);
        const __half2 a1h = __float2half2_rn(a1);
        const __half2 a2h = __float2half2_rn(a2);

        const __half2 gvh = __hfma2(a0h, ec0, __hfma2(a1h, ec1, __hmul2(a2h, ec2)));
        const __half2 n0h = __hmul2(gvh, eci);

        __half2 h[8];
        #pragma unroll
        for (int j = 0; j < 8; j++)
            h[j] = __hfma2(n0h, w1h[0][j],
                   __hfma2(gvh, w1h[1][j], __hmul2(eci, w1h[2][j])));

        // Value-splitting reduce of 8 packed values over the 16-lane group.
        __half2 t[4];
        #pragma unroll
        for (int k = 0; k < 4; k++) {               // off=8: 8 -> 4
            const __half2 snd = q3 ? h[k] : h[k + 4];
            const __half2 rcv = shfl_xor_h2(snd, 8);
            t[k] = __hadd2(q3 ? h[k + 4] : h[k], rcv);
        }
        __half2 u[2];
        #pragma unroll
        for (int k = 0; k < 2; k++) {               // off=4: 4 -> 2
            const __half2 snd = q2b ? t[k] : t[k + 2];
            const __half2 rcv = shfl_xor_h2(snd, 4);
            u[k] = __hadd2(q2b ? t[k + 2] : t[k], rcv);
        }
        {
            const __half2 snd = q1b ? u[0] : u[1];  // off=2: 2 -> 1
            const __half2 rcv = shfl_xor_h2(snd, 2);
            u[0] = __hadd2(q1b ? u[1] : u[0], rcv);
        }
        const __half2 hh2 = __hadd2(u[0], shfl_xor_h2(u[0], 1));
        const float hh = __low2float(hh2) + __high2float(hh2);
        // hh = complete h_jm, jm = (lane>>1)&7 within this sample's group.

        float p = fmaxf(hh + b1j, 0.0f) * w2j;
        p += __shfl_xor_sync(FULLMASK, p, 2);       // orbit over lane bits 1..3
        p += __shfl_xor_sync(FULLMASK, p, 4);
        p += __shfl_xor_sync(FULLMASK, p, 8);

        const float y = __fdividef(1.0f, 1.0f + __expf(-(p + b2)));
        if (sub == 0 && vC) out[scur] = y;

        if (bn >= n) break;                          // nothing left anywhere

        // ---- rotate pipeline state (convert incoming f32 pairs to half2) ----
        bc = bn;  scur = bc + half;  vC = (scur < n);
        ec0 = en0; ec1 = en1; ec2 = en2v; eci = eni;
        en0  = __floats2half2_rn(fa.x, fa.y);
        en1  = __floats2half2_rn(fb.x, fb.y);
        en2v = __floats2half2_rn(fc.x, fc.y);
        eni  = __floats2half2_rn(fd.x, fd.y);
        bn = bq; bq = br;
        m2a = m3a; m2b = m3b; m2c = m3c; it2 = it3;
    }
}

extern "C" void kernel_launch(void* const* d_in, const int* in_sizes, int n_in,
                              void* d_out, int out_size)
{
    (void)n_in; (void)out_size;
    const int*   group_inputs = (const int*)  d_in[0];
    const int*   item_inputs  = (const int*)  d_in[1];
    const int*   members      = (const int*)  d_in[2];
    const float* user_emb     = (const float*)d_in[3];
    const float* item_emb     = (const float*)d_in[4];
    const float* genres       = (const float*)d_in[5];
    const float* attn_W       = (const float*)d_in[6];
    const float* attn_b       = (const float*)d_in[7];
    const float* pred_W1      = (const float*)d_in[8];
    const float* pred_b1      = (const float*)d_in[9];
    const float* pred_W2      = (const float*)d_in[10];
    const float* pred_b2      = (const float*)d_in[11];
    float* out = (float*)d_out;
    const int n = in_sizes[0];

    // 2048 blocks x 4 warps x 2 samples = 16384 slots -> 8 iterations each.
    const int blocks = 2048;
    bahdanau_kernel<<<blocks, 128>>>(group_inputs, item_inputs, members,
                                     user_emb, item_emb, genres,
                                     attn_W, attn_b, pred_W1, pred_b1,
                                     pred_W2, pred_b2, out, n);
}

// round 17
// speedup vs baseline: 1.8633x; 1.8633x over previous
#include <cuda_runtime.h>

// BAHDANAUplus — R15: pure-f32 compute (R7 structure: 16 lanes/sample,
// 2 samples/warp, 2 dims/lane as float2), with pred_W1 moved to SHARED
// memory (conflict-free float2 reads, broadcast across the two halves)
// to cut ~48 registers -> higher occupancy. Depth-3 software pipeline.

#define FULLMASK 0xffffffffu

__global__ __launch_bounds__(128, 6) void bahdanau_kernel(
    const int*   __restrict__ group_inputs,
    const int*   __restrict__ item_inputs,
    const int*   __restrict__ members,
    const float* __restrict__ user_emb,
    const float* __restrict__ item_emb,
    const float* __restrict__ genres,
    const float* __restrict__ attn_W,
    const float* __restrict__ attn_b,
    const float* __restrict__ pred_W1,
    const float* __restrict__ pred_b1,
    const float* __restrict__ pred_W2,
    const float* __restrict__ pred_b2,
    float*       __restrict__ out,
    int n)
{
    // ---- stage pred_W1 into shared: w1s[(j*3+seg)*32 + d] = W1[seg*32+d][j]
    // Lane reads float2 at d = 2*sub -> 16 lanes cover one 128B row,
    // conflict-free; the two sample-halves broadcast. 768 floats = 3 KB.
    __shared__ float w1s[768];
    for (int i = threadIdx.x; i < 768; i += 128) {
        const int j   = i / 96;
        const int r   = i - j * 96;
        const int seg = r >> 5;
        const int d   = r & 31;
        w1s[i] = pred_W1[(seg * 32 + d) * 8 + j];
    }
    __syncthreads();

    const int lane = threadIdx.x & 31;
    const int sub  = lane & 15;          // position within the sample's 16-lane group
    const int half = lane >> 4;          // which sample of the pair
    const int wid  = threadIdx.x >> 5;
    const int gw   = blockIdx.x * 4 + wid;
    const int nwarp  = gridDim.x * 4;
    const int stride = nwarp * 2;        // samples consumed per iteration

    const int d0 = sub * 2;              // this lane's first dim

    // ---- attn_W in registers: rows {d0, d0+1} of each 32-row segment ----
    float aw[2][4][3];                   // [dim][segment][k]
    #pragma unroll
    for (int seg = 0; seg < 4; seg++) {
        const float2* p = (const float2*)(attn_W + (seg * 32 + d0) * 3);
        const float2 q0 = p[0], q1 = p[1], q2 = p[2];
        aw[0][seg][0] = q0.x; aw[0][seg][1] = q0.y; aw[0][seg][2] = q1.x;
        aw[1][seg][0] = q1.y; aw[1][seg][1] = q2.x; aw[1][seg][2] = q2.y;
    }

    const float ab0 = attn_b[0], ab1 = attn_b[1], ab2 = attn_b[2];
    const int   jm  = (lane >> 1) & 7;   // hidden unit owned after value-split
    const float b1j = pred_b1[jm];
    const float w2j = pred_W2[jm];
    const float b2  = pred_b2[0];

    const bool q3  = (lane & 8) != 0;
    const bool q2b = (lane & 4) != 0;
    const bool q1b = (lane & 2) != 0;

    const float2* ue = (const float2*)user_emb;   // 16 float2 per row
    const float2* ie = (const float2*)item_emb;   // 7 float2 per row
    const float2* ge = (const float2*)genres;     // 9 float2 per row

    int bc = gw * 2;                     // iteration base; my sample = bc + half
    if (bc >= n) return;

    // ---- prologue: fill 3-deep pipeline ----
    int  scur = bc + half;
    bool vC   = (scur < n);
    float2 ec0, ec1, ec2, eci;           // current sample
    {
        const int sl = vC ? scur : 0;
        const int g  = group_inputs[sl];
        const int it = item_inputs[sl];
        const int m0 = members[3 * g + 0];
        const int m1 = members[3 * g + 1];
        const int m2 = members[3 * g + 2];
        ec0 = ue[m0 * 16 + sub];
        ec1 = ue[m1 * 16 + sub];
        ec2 = ue[m2 * 16 + sub];
        eci = (sub < 7) ? ie[it * 7 + sub] : ge[it * 9 + (sub - 7)];
    }

    int  bn  = bc + stride;
    float2 en0, en1, en2v, eni;          // next sample
    {
        const int sx = bn + half;
        const int sl = (sx < n) ? sx : 0;
        const int g  = group_inputs[sl];
        const int it = item_inputs[sl];
        const int m0 = members[3 * g + 0];
        const int m1 = members[3 * g + 1];
        const int m2 = members[3 * g + 2];
        en0  = ue[m0 * 16 + sub];
        en1  = ue[m1 * 16 + sub];
        en2v = ue[m2 * 16 + sub];
        eni  = (sub < 7) ? ie[it * 7 + sub] : ge[it * 9 + (sub - 7)];
    }

    int bq = bn + stride;                // sample i+2: indices only
    int m2a, m2b, m2c, it2;
    {
        const int sx = bq + half;
        const int sl = (sx < n) ? sx : 0;
        const int g  = group_inputs[sl];
        it2 = item_inputs[sl];
        m2a = members[3 * g + 0];
        m2b = members[3 * g + 1];
        m2c = members[3 * g + 2];
    }

    for (;;) {
        // ---- stage 1: issue gathers for sample i+2 (consumed in 2 iters) ----
        const float2 fa = ue[m2a * 16 + sub];
        const float2 fb = ue[m2b * 16 + sub];
        const float2 fc = ue[m2c * 16 + sub];
        const float2 fd = (sub < 7) ? ie[it2 * 7 + sub] : ge[it2 * 9 + (sub - 7)];

        // ---- stage 2: prefetch index chain for sample i+3 ----
        const int br = bq + stride;
        int m3a, m3b, m3c, it3;
        {
            const int sx = br + half;
            const int sl = (sx < n) ? sx : 0;
            const int g  = group_inputs[sl];
            it3 = item_inputs[sl];
            m3a = members[3 * g + 0];
            m3b = members[3 * g + 1];
            m3c = members[3 * g + 2];
        }

        // ---- stage 3: compute current sample ----
        float v0 = ec0.x * aw[0][0][0] + ec0.y * aw[1][0][0]
                 + ec1.x * aw[0][1][0] + ec1.y * aw[1][1][0]
                 + ec2.x * aw[0][2][0] + ec2.y * aw[1][2][0]
                 + eci.x * aw[0][3][0] + eci.y * aw[1][3][0];
        float v1 = ec0.x * aw[0][0][1] + ec0.y * aw[1][0][1]
                 + ec1.x * aw[0][1][1] + ec1.y * aw[1][1][1]
                 + ec2.x * aw[0][2][1] + ec2.y * aw[1][2][1]
                 + eci.x * aw[0][3][1] + eci.y * aw[1][3][1];
        float v2 = ec0.x * aw[0][0][2] + ec0.y * aw[1][0][2]
                 + ec1.x * aw[0][1][2] + ec1.y * aw[1][1][2]
                 + ec2.x * aw[0][2][2] + ec2.y * aw[1][2][2]
                 + eci.x * aw[0][3][2] + eci.y * aw[1][3][2];

        // Butterfly over the 16-lane group (both samples share instructions).
        #pragma unroll
        for (int off = 8; off > 0; off >>= 1) {
            v0 += __shfl_xor_sync(FULLMASK, v0, off);
            v1 += __shfl_xor_sync(FULLMASK, v1, off);
            v2 += __shfl_xor_sync(FULLMASK, v2, off);
        }
        const float a0 = v0 + ab0;
        const float a1 = v1 + ab1;
        const float a2 = v2 + ab2;

        float2 gv, n0;
        gv.x = a0 * ec0.x + a1 * ec1.x + a2 * ec2.x;
        gv.y = a0 * ec0.y + a1 * ec1.y + a2 * ec2.y;
        n0.x = gv.x * eci.x;
        n0.y = gv.y * eci.y;

        // MLP hidden units: W1 from shared (conflict-free float2 per seg).
        float h[8];
        #pragma unroll
        for (int j = 0; j < 8; j++) {
            const float2 wa = *(const float2*)&w1s[(j * 3 + 0) * 32 + d0];
            const float2 wb = *(const float2*)&w1s[(j * 3 + 1) * 32 + d0];
            const float2 wc = *(const float2*)&w1s[(j * 3 + 2) * 32 + d0];
            h[j] = n0.x * wa.x + n0.y * wa.y
                 + gv.x * wb.x + gv.y * wb.y
                 + eci.x * wc.x + eci.y * wc.y;
        }

        // Value-splitting reduce of 8 values over the 16-lane group.
        float t[4];
        #pragma unroll
        for (int k = 0; k < 4; k++) {               // off=8: 8 -> 4
            const float snd = q3 ? h[k] : h[k + 4];
            const float rcv = __shfl_xor_sync(FULLMASK, snd, 8);
            t[k] = (q3 ? h[k + 4] : h[k]) + rcv;
        }
        float u[2];
        #pragma unroll
        for (int k = 0; k < 2; k++) {               // off=4: 4 -> 2
            const float snd = q2b ? t[k] : t[k + 2];
            const float rcv = __shfl_xor_sync(FULLMASK, snd, 4);
            u[k] = (q2b ? t[k + 2] : t[k]) + rcv;
        }
        {
            const float snd = q1b ? u[0] : u[1];    // off=2: 2 -> 1
            const float rcv = __shfl_xor_sync(FULLMASK, snd, 2);
            u[0] = (q1b ? u[1] : u[0]) + rcv;
        }
        float hh = u[0] + __shfl_xor_sync(FULLMASK, u[0], 1);
        // hh = complete h_jm, jm = (lane>>1)&7 within this sample's group.

        float p = fmaxf(hh + b1j, 0.0f) * w2j;
        p += __shfl_xor_sync(FULLMASK, p, 2);       // orbit over lane bits 1..3
        p += __shfl_xor_sync(FULLMASK, p, 4);
        p += __shfl_xor_sync(FULLMASK, p, 8);

        const float y = __fdividef(1.0f, 1.0f + __expf(-(p + b2)));
        if (sub == 0 && vC) out[scur] = y;

        if (bn >= n) break;                          // nothing left anywhere

        // ---- rotate pipeline state ----
        bc = bn;  scur = bc + half;  vC = (scur < n);
        ec0 = en0; ec1 = en1; ec2 = en2v; eci = eni;
        en0 = fa; en1 = fb; en2v = fc; eni = fd;
        bn = bq; bq = br;
        m2a = m3a; m2b = m3b; m2c = m3c; it2 = it3;
    }
}

extern "C" void kernel_launch(void* const* d_in, const int* in_sizes, int n_in,
                              void* d_out, int out_size)
{
    (void)n_in; (void)out_size;
    const int*   group_inputs = (const int*)  d_in[0];
    const int*   item_inputs  = (const int*)  d_in[1];
    const int*   members      = (const int*)  d_in[2];
    const float* user_emb     = (const float*)d_in[3];
    const float* item_emb     = (const float*)d_in[4];
    const float* genres       = (const float*)d_in[5];
    const float* attn_W       = (const float*)d_in[6];
    const float* attn_b       = (const float*)d_in[7];
    const float* pred_W1      = (const float*)d_in[8];
    const float* pred_b1      = (const float*)d_in[9];
    const float* pred_W2      = (const float*)d_in[10];
    const float* pred_b2      = (const float*)d_in[11];
    float* out = (float*)d_out;
    const int n = in_sizes[0];

    // 2048 blocks x 4 warps x 2 samples = 16384 slots -> 8 iterations each.
    const int blocks = 2048;
    bahdanau_kernel<<<blocks, 128>>>(group_inputs, item_inputs, members,
                                     user_emb, item_emb, genres,
                                     attn_W, attn_b, pred_W1, pred_b1,
                                     pred_W2, pred_b2, out, n);
}